// round 1
// baseline (speedup 1.0000x reference)
#include <cuda_runtime.h>
#include <cuda_bf16.h>
#include <cstdint>

#define TAU_F 0.3f
#define EPS_F 1e-8f

static constexpr int NT = 256;       // threads per block (pass 1)
static constexpr int NB = 4096;      // blocks (pass 1) -> 1,048,576 threads = 1 box/thread for B*N
static constexpr int NT2 = 1024;     // threads (pass 2, single block)

// Scratch for block partial sums: .x = masked loss sum, .y = mask count
__device__ float2 g_partials[NB];

__device__ __forceinline__ float warp_sum(float v) {
    #pragma unroll
    for (int off = 16; off > 0; off >>= 1)
        v += __shfl_xor_sync(0xFFFFFFFFu, v, off);
    return v;
}

__global__ __launch_bounds__(NT) void gwd_pass1(
    const float* __restrict__ pred,
    const float* __restrict__ gt,
    int total)
{
    float lsum = 0.0f;
    float msum = 0.0f;

    for (int i = blockIdx.x * NT + threadIdx.x; i < total; i += gridDim.x * NT) {
        const float* p = pred + 7 * i;
        const float* g = gt   + 7 * i;

        // 14 independent loads -> high MLP; contiguous 28B/thread across warp
        float p0 = __ldg(p + 0), p1 = __ldg(p + 1), p2 = __ldg(p + 2);
        float p3 = __ldg(p + 3), p4 = __ldg(p + 4), p5 = __ldg(p + 5);
        float p6 = __ldg(p + 6);
        float g0 = __ldg(g + 0), g1 = __ldg(g + 1), g2 = __ldg(g + 2);
        float g3 = __ldg(g + 3), g4 = __ldg(g + 4), g5 = __ldg(g + 5);
        float g6 = __ldg(g + 6);

        // ---- mean distance ----
        float dx = p0 - g0, dy = p1 - g1, dz = p2 - g2;
        float mu_dist = dx * dx + dy * dy + dz * dz;

        // ---- eigenvalues of the diagonal (pre-rotation) covariances ----
        float ap = 0.25f * p3 * p3, bp = 0.25f * p4 * p4, cp = 0.25f * p5 * p5;
        float at = 0.25f * g3 * g3, bt = 0.25f * g4 * g4, ct = 0.25f * g5 * g5;

        // sqrtm_psd(sigma_p) clips sigma_p eigenvalues at EPS
        float a = fmaxf(ap, EPS_F);
        float b = fmaxf(bp, EPS_F);
        float c = fmaxf(cp, EPS_F);

        // ---- 2x2 xy block of M = sqrt(Sp) St sqrt(Sp) ----
        float cd = __cosf(p6 - g6);
        float cc = cd * cd;
        float ss = 1.0f - cc;
        float trM  = cc * fmaf(a, at, b * bt) + ss * fmaf(a, bt, b * at);
        float detM = (a * b) * (at * bt);

        // eigenvalues of M, clipped at EPS (matches second sqrtm_psd clip)
        float disc = fmaxf(fmaf(trM, trM, -4.0f * detM), 0.0f);
        float sq   = sqrtf(disc);
        float l1   = fmaxf(0.5f * (trM + sq), EPS_F);
        float l2   = fmaxf(0.5f * (trM - sq), EPS_F);
        float tr_sqrtM = sqrtf(l1) + sqrtf(l2);

        // z scalar block: eigenvalue of M_z = c * ct, clipped at EPS
        float sz = sqrtf(fmaxf(c * ct, EPS_F));

        // cov term uses RAW traces of sigma_p, sigma_t
        float cov = (ap + bp + cp) + (at + bt + ct) - 2.0f * (tr_sqrtM + sz);
        float w2  = mu_dist + cov;

        // det(sigma_t) clipped, then cube root
        float detT  = fmaxf(at * bt * ct, EPS_F);
        float dterm = __expf(__logf(detT) * (1.0f / 3.0f));

        float loss = 1.0f - __expf(-w2 / (TAU_F * dterm));
        float mask = (g0 != 0.0f) ? 1.0f : 0.0f;

        lsum = fmaf(loss, mask, lsum);
        msum += mask;
    }

    // ---- block reduction ----
    lsum = warp_sum(lsum);
    msum = warp_sum(msum);

    __shared__ float sl[NT / 32];
    __shared__ float sm[NT / 32];
    int lane = threadIdx.x & 31;
    int wid  = threadIdx.x >> 5;
    if (lane == 0) { sl[wid] = lsum; sm[wid] = msum; }
    __syncthreads();

    if (wid == 0) {
        float vl = (lane < NT / 32) ? sl[lane] : 0.0f;
        float vm = (lane < NT / 32) ? sm[lane] : 0.0f;
        vl = warp_sum(vl);
        vm = warp_sum(vm);
        if (lane == 0) g_partials[blockIdx.x] = make_float2(vl, vm);
    }
}

__global__ __launch_bounds__(NT2) void gwd_pass2(float* __restrict__ out)
{
    // deterministic tree reduction of NB partials in double precision
    double l = 0.0, m = 0.0;
    for (int i = threadIdx.x; i < NB; i += NT2) {
        float2 v = g_partials[i];
        l += (double)v.x;
        m += (double)v.y;
    }

    __shared__ double shl[NT2 / 32];
    __shared__ double shm[NT2 / 32];

    #pragma unroll
    for (int off = 16; off > 0; off >>= 1) {
        l += __shfl_xor_sync(0xFFFFFFFFu, l, off);
        m += __shfl_xor_sync(0xFFFFFFFFu, m, off);
    }
    int lane = threadIdx.x & 31;
    int wid  = threadIdx.x >> 5;
    if (lane == 0) { shl[wid] = l; shm[wid] = m; }
    __syncthreads();

    if (wid == 0) {
        double vl = (lane < NT2 / 32) ? shl[lane] : 0.0;
        double vm = (lane < NT2 / 32) ? shm[lane] : 0.0;
        #pragma unroll
        for (int off = 16; off > 0; off >>= 1) {
            vl += __shfl_xor_sync(0xFFFFFFFFu, vl, off);
            vm += __shfl_xor_sync(0xFFFFFFFFu, vm, off);
        }
        if (lane == 0)
            out[0] = (float)(vl / (vm + (double)EPS_F));
    }
}

extern "C" void kernel_launch(void* const* d_in, const int* in_sizes, int n_in,
                              void* d_out, int out_size)
{
    const float* pred = (const float*)d_in[0];
    const float* gt   = (const float*)d_in[1];
    float* out = (float*)d_out;

    int total = in_sizes[0] / 7;

    gwd_pass1<<<NB, NT>>>(pred, gt, total);
    gwd_pass2<<<1, NT2>>>(out);
}

// round 2
// speedup vs baseline: 1.2166x; 1.2166x over previous
#include <cuda_runtime.h>
#include <cuda_bf16.h>
#include <cstdint>

#define TAU_F 0.3f
#define EPS_F 1e-8f

static constexpr int NT  = 256;                 // threads per block
static constexpr int NB1 = 1184;                // 148 SMs * 8 CTAs
static constexpr int FLOATS_PER_TILE = NT * 7;  // 1792 floats = 448 float4

__device__ float2       g_partials[NB1];
__device__ unsigned int g_done_count;           // static-init 0; reset by last block

__device__ __forceinline__ float warp_sum(float v) {
    #pragma unroll
    for (int off = 16; off > 0; off >>= 1)
        v += __shfl_xor_sync(0xFFFFFFFFu, v, off);
    return v;
}

__global__ __launch_bounds__(NT) void gwd_fused(
    const float* __restrict__ pred,
    const float* __restrict__ gt,
    float* __restrict__ out,
    int total)
{
    __shared__ float sp[FLOATS_PER_TILE];
    __shared__ float sg[FLOATS_PER_TILE];

    const int ntiles = (total + NT - 1) / NT;

    float lsum = 0.0f;
    float msum = 0.0f;

    for (int tile = blockIdx.x; tile < ntiles; tile += gridDim.x) {
        const long long base   = (long long)tile * FLOATS_PER_TILE;
        const long long remain = (long long)total * 7 - base;

        if (remain >= FLOATS_PER_TILE) {
            // fast path: full tile, vectorized LDG.128 (base is 16B-aligned:
            // 1792 floats/tile * 4B = 7168B, multiple of 16)
            const float4* __restrict__ p4 = (const float4*)(pred + base);
            const float4* __restrict__ g4 = (const float4*)(gt   + base);
            float4* __restrict__ sp4 = (float4*)sp;
            float4* __restrict__ sg4 = (float4*)sg;
            #pragma unroll
            for (int i = threadIdx.x; i < FLOATS_PER_TILE / 4; i += NT) {
                sp4[i] = p4[i];
                sg4[i] = g4[i];
            }
        } else {
            for (int i = threadIdx.x; i < (int)remain; i += NT) {
                sp[i] = pred[base + i];
                sg[i] = gt[base + i];
            }
        }
        __syncthreads();

        const int box = tile * NT + threadIdx.x;
        if (box < total) {
            const float* p = sp + 7 * threadIdx.x;
            const float* g = sg + 7 * threadIdx.x;

            float p0 = p[0], p1 = p[1], p2 = p[2], p3 = p[3], p4v = p[4], p5 = p[5], p6 = p[6];
            float g0 = g[0], g1 = g[1], g2 = g[2], g3 = g[3], g4v = g[4], g5 = g[5], g6 = g[6];

            // ---- mean distance ----
            float dx = p0 - g0, dy = p1 - g1, dz = p2 - g2;
            float mu_dist = dx * dx + dy * dy + dz * dz;

            // ---- diagonal covariance eigenvalues ----
            float ap = 0.25f * p3 * p3, bp = 0.25f * p4v * p4v, cp = 0.25f * p5 * p5;
            float at = 0.25f * g3 * g3, bt = 0.25f * g4v * g4v, ct = 0.25f * g5 * g5;

            // sqrtm_psd(sigma_p) clips sigma_p eigenvalues at EPS
            float a = fmaxf(ap, EPS_F);
            float b = fmaxf(bp, EPS_F);
            float c = fmaxf(cp, EPS_F);

            // ---- 2x2 xy block of M = sqrt(Sp) St sqrt(Sp) ----
            float cd = __cosf(p6 - g6);
            float cc = cd * cd;
            float ss = 1.0f - cc;
            float trM  = cc * fmaf(a, at, b * bt) + ss * fmaf(a, bt, b * at);
            float detM = (a * b) * (at * bt);

            float disc = fmaxf(fmaf(trM, trM, -4.0f * detM), 0.0f);
            float sq   = sqrtf(disc);
            float l1   = fmaxf(0.5f * (trM + sq), EPS_F);
            float l2   = fmaxf(0.5f * (trM - sq), EPS_F);
            float tr_sqrtM = sqrtf(l1) + sqrtf(l2);

            // z scalar block
            float sz = sqrtf(fmaxf(c * ct, EPS_F));

            float cov = (ap + bp + cp) + (at + bt + ct) - 2.0f * (tr_sqrtM + sz);
            float w2  = mu_dist + cov;

            float detT  = fmaxf(at * bt * ct, EPS_F);
            float dterm = __expf(__logf(detT) * (1.0f / 3.0f));

            float loss = 1.0f - __expf(-w2 / (TAU_F * dterm));
            float mask = (g0 != 0.0f) ? 1.0f : 0.0f;

            lsum = fmaf(loss, mask, lsum);
            msum += mask;
        }
        __syncthreads();
    }

    // ---- block reduction ----
    lsum = warp_sum(lsum);
    msum = warp_sum(msum);

    __shared__ float sl[NT / 32];
    __shared__ float sm[NT / 32];
    int lane = threadIdx.x & 31;
    int wid  = threadIdx.x >> 5;
    if (lane == 0) { sl[wid] = lsum; sm[wid] = msum; }
    __syncthreads();

    __shared__ bool is_last;
    if (threadIdx.x == 0) {
        float vl = 0.0f, vm = 0.0f;
        #pragma unroll
        for (int w = 0; w < NT / 32; w++) { vl += sl[w]; vm += sm[w]; }
        g_partials[blockIdx.x] = make_float2(vl, vm);
        __threadfence();
        unsigned int ticket = atomicAdd(&g_done_count, 1u);
        is_last = (ticket == (unsigned)(gridDim.x - 1));
    }
    __syncthreads();

    // ---- last block finalizes (deterministic: fixed summation order) ----
    if (is_last) {
        double l = 0.0, m = 0.0;
        for (int i = threadIdx.x; i < NB1; i += NT) {
            float2 v = g_partials[i];
            l += (double)v.x;
            m += (double)v.y;
        }
        #pragma unroll
        for (int off = 16; off > 0; off >>= 1) {
            l += __shfl_xor_sync(0xFFFFFFFFu, l, off);
            m += __shfl_xor_sync(0xFFFFFFFFu, m, off);
        }
        __shared__ double dl[NT / 32];
        __shared__ double dm[NT / 32];
        if (lane == 0) { dl[wid] = l; dm[wid] = m; }
        __syncthreads();
        if (threadIdx.x == 0) {
            double vl = 0.0, vm = 0.0;
            #pragma unroll
            for (int w = 0; w < NT / 32; w++) { vl += dl[w]; vm += dm[w]; }
            out[0] = (float)(vl / (vm + (double)EPS_F));
            g_done_count = 0;   // reset for next graph replay
        }
    }
}

extern "C" void kernel_launch(void* const* d_in, const int* in_sizes, int n_in,
                              void* d_out, int out_size)
{
    const float* pred = (const float*)d_in[0];
    const float* gt   = (const float*)d_in[1];
    float* out = (float*)d_out;

    int total = in_sizes[0] / 7;

    gwd_fused<<<NB1, NT>>>(pred, gt, out, total);
}